// round 8
// baseline (speedup 1.0000x reference)
#include <cuda_runtime.h>

typedef unsigned long long ull;

#define NBLK 128
#define BH   65536
#define Tq   40
#define VOCq 10000

__device__ float g_P[3][Tq * BH];
__device__ float g_C[3][BH];
__device__ float g_H0B[2][BH];
__device__ float g_H1[BH];
__device__ float g_Z0[BH];
__device__ float g_RH0[BH];
__device__ float g_Z1[BH];
__device__ float g_RH1[BH];
__device__ float g_H1seq[Tq * BH];
__device__ unsigned g_cnt;

__device__ __forceinline__ ull pk2(float x, float y) {
    ull r; asm("mov.b64 %0, {%1,%2};" : "=l"(r) : "f"(x), "f"(y)); return r;
}
__device__ __forceinline__ void upk2(ull v, float &x, float &y) {
    asm("mov.b64 {%0,%1}, %2;" : "=f"(x), "=f"(y) : "l"(v));
}
__device__ __forceinline__ void fma2(ull &c, ull a, ull b) {
    asm("fma.rn.f32x2 %0, %1, %2, %3;" : "=l"(c) : "l"(a), "l"(b), "l"(c));
}

__device__ __forceinline__ void gridbar(unsigned &target) {
    __syncthreads();
    target += NBLK;
    if (threadIdx.x == 0) {
        asm volatile("red.release.gpu.add.u32 [%0], %1;" :: "l"(&g_cnt), "r"(1u) : "memory");
        unsigned v;
        do {
            asm volatile("ld.acquire.gpu.u32 %0, [%1];" : "=r"(v) : "l"(&g_cnt) : "memory");
        } while (v < target);
    }
    __syncthreads();
}

// ---------------- 32x64 recurrence tile, 512 threads ----------------
// 4x4 warp grid: warp = 8 rows x 16 cols; lane = 2 rows x 2 cols.
// Per kk per lane: 1 LDS128 (dup-A pair) + 1 LDS64 (W) + 2 FFMA2.
// A = concat(A1,A2) at k=512. mode 0: sigm(v+add)[*mulS]; mode 1: GRU update.
__device__ __noinline__ void gtile(float *sA, float *sW, int m0, int n0, int K,
    const float *A1, const float *A2, const float *W,
    const float *addRow, const float *addMat, int mode,
    const float *mulS, const float *hPrev, const float *zG,
    float *dst, float *dst2)
{
    constexpr int AS = 68;                       // dup-A row pitch (floats)
    const int tid = threadIdx.x, lane = tid & 31, w = tid >> 5;
    const int wr = w >> 2, wc = w & 3, rp = lane >> 3, cp = lane & 7;
    const int aoff = 16 * wr + 4 * rp;           // smem float offset of dup row pair
    const int woff = 16 * wc + 2 * cp;

    __syncthreads();

    ull acc0 = 0ull, acc1 = 0ull;

    auto ald = [&](int kb, int j) -> float {
        int idx = tid + j * 512;                 // 1024 elems: k=idx&31, m=idx>>5
        int k = kb + (idx & 31);
        const float *b = (k < 512) ? A1 : A2;
        return b[(m0 + (idx >> 5)) * 512 + (k & 511)];
    };

    float ra[2]; float4 rw;
#pragma unroll
    for (int j = 0; j < 2; j++) ra[j] = ald(0, j);
    rw = *(const float4 *)(W + (size_t)(tid >> 4) * 512 + n0 + (tid & 15) * 4);
#pragma unroll
    for (int j = 0; j < 2; j++) {
        int idx = tid + j * 512;
        *(ull *)(sA + (idx & 31) * AS + 2 * (idx >> 5)) = pk2(ra[j], ra[j]);
    }
    *(float4 *)(sW + (tid >> 4) * 64 + (tid & 15) * 4) = rw;
    __syncthreads();

    const int niter = K >> 5;
    for (int it = 0; it < niter; ++it) {
        if (it + 1 < niter) {
            int kb = (it + 1) << 5;
#pragma unroll
            for (int j = 0; j < 2; j++) ra[j] = ald(kb, j);
            rw = *(const float4 *)(W + (size_t)(kb + (tid >> 4)) * 512 + n0 + (tid & 15) * 4);
        }
        const float *A0 = sA + (it & 1) * 32 * AS;
        const float *W0 = sW + (it & 1) * 32 * 64;
#pragma unroll
        for (int kk = 0; kk < 32; kk++) {
            ulonglong2 av = *(const ulonglong2 *)(A0 + kk * AS + aoff);
            ull wv = *(const ull *)(W0 + kk * 64 + woff);
            fma2(acc0, av.x, wv);
            fma2(acc1, av.y, wv);
        }
        if (it + 1 < niter) {
            float *An = sA + ((it + 1) & 1) * 32 * AS;
            float *Wn = sW + ((it + 1) & 1) * 32 * 64;
#pragma unroll
            for (int j = 0; j < 2; j++) {
                int idx = tid + j * 512;
                *(ull *)(An + (idx & 31) * AS + 2 * (idx >> 5)) = pk2(ra[j], ra[j]);
            }
            *(float4 *)(Wn + (tid >> 4) * 64 + (tid & 15) * 4) = rw;
            __syncthreads();
        }
    }

    const int r0 = m0 + 8 * wr + 2 * rp, c0 = n0 + 16 * wc + 2 * cp;
#pragma unroll
    for (int i = 0; i < 2; i++) {
        float lh[2]; upk2(i ? acc1 : acc0, lh[0], lh[1]);
        int row = r0 + i;
#pragma unroll
        for (int e = 0; e < 2; e++) {
            int c = c0 + e, idx = row * 512 + c;
            float x = lh[e] + (addRow ? addRow[c] : addMat[idx]);
            if (mode == 0) {
                float s = __fdividef(1.f, 1.f + __expf(-x));
                dst[idx] = mulS ? s * mulS[idx] : s;
            } else {
                float ex = __expf(2.f * x);
                float hh = 1.f - __fdividef(2.f, ex + 1.f);
                float z = zG[idx];
                float hn = z * hPrev[idx] + (1.f - z) * hh;
                dst[idx] = hn;
                if (dst2) dst2[idx] = hn;
            }
        }
    }
}

// ---------------- persistent recurrence: 128 blocks x 512 threads ----------
// ZR-phase(t): b<64 -> ZR1(t) 32x64 K=1024; b>=64 -> ZR0(t+1) 32x64 K=512
// H-phase(t):  b<32 -> H1(t-1) 32x64 K=1024; b in [64,96) -> H0(t) K=512
__global__ __launch_bounds__(512, 1) void k_recur(
    const float *wu0, const float *wr0, const float *wc0,
    const float *wu1, const float *bu1, const float *wr1, const float *br1,
    const float *wc1, const float *bc1)
{
    __shared__ __align__(16) float sA[2 * 32 * 68];
    __shared__ __align__(16) float sW[2 * 32 * 64];
    unsigned target = 0;
    const int b = blockIdx.x;

    auto ZR = [&](int t) {
        if (b < 64) {
            if (t < 0) return;
            int gate = b >> 5, id = b & 31;
            int m0 = (id >> 3) * 32, n0 = (id & 7) * 64;
            gtile(sA, sW, m0, n0, 1024, g_H1, g_H0B[t & 1],
                  gate ? wr1 : wu1, gate ? br1 : bu1, nullptr, 0,
                  gate ? (const float *)g_H1 : nullptr, nullptr, nullptr,
                  gate ? g_RH1 : g_Z1, nullptr);
        } else {
            int tn = t + 1;
            if (tn > 39) return;
            int s = b - 64, gate = s >> 5, id = s & 31;
            int m0 = (id >> 3) * 32, n0 = (id & 7) * 64;
            const float *Hp = g_H0B[t & 1];             // t=-1 -> buf1 (zeros)
            gtile(sA, sW, m0, n0, 512, Hp, Hp,
                  gate ? wr0 : wu0, nullptr, g_P[gate] + (size_t)tn * BH, 0,
                  gate ? Hp : nullptr, nullptr, nullptr,
                  gate ? g_RH0 : g_Z0, nullptr);
        }
    };
    auto HP = [&](int t) {
        if (b < 32) {                                   // H1(t-1), K=1024
            int tp = t - 1;
            if (tp < 0) return;
            int m0 = (b >> 3) * 32, n0 = (b & 7) * 64;
            gtile(sA, sW, m0, n0, 1024, g_RH1, g_H0B[tp & 1], wc1,
                  bc1, nullptr, 1, nullptr, g_H1, g_Z1,
                  g_H1, g_H1seq + (size_t)tp * BH);
        } else if (b >= 64 && b < 96) {                 // H0(t), K=512
            if (t > 39) return;
            int s = b - 64, m0 = (s >> 3) * 32, n0 = (s & 7) * 64;
            gtile(sA, sW, m0, n0, 512, g_RH0, g_RH0, wc0,
                  nullptr, g_P[2] + (size_t)t * BH, 1,
                  nullptr, g_H0B[(t - 1) & 1], g_Z0,
                  g_H0B[t & 1], nullptr);
        }
    };

    ZR(-1); gridbar(target);
    for (int t = 0; t < Tq; t++) {
        HP(t); gridbar(target);
        ZR(t); gridbar(target);
    }
    HP(Tq);
}

// ---------------- big parallel GEMM core (unchanged) ----------------
template<int BM, int BN, int BK, int TM, int TN, int THREADS,
         class AF, class WF, class EF>
__device__ __forceinline__ void core(float *sA, float *sW, int tid,
                                     int K, AF aload, WF wload, EF epi)
{
    constexpr int NT = BN / TN, MT = BM / TM, TN2 = TN / 2;
    constexpr int AS = 2 * BM + 4;
    constexpr int ALD = BM * BK / THREADS, WLD = BK * BN / THREADS;
    static_assert(NT * MT == THREADS, "");
    const int tx = tid % NT, ty = tid / NT;
    __syncthreads();
    ull acc[TM][TN2];
#pragma unroll
    for (int i = 0; i < TM; i++)
#pragma unroll
        for (int j = 0; j < TN2; j++) acc[i][j] = 0ull;
#pragma unroll
    for (int j = 0; j < ALD; j++) {
        int idx = tid + j * THREADS;
        float v = aload(idx % BK, idx / BK);
        *(ull *)(sA + (idx % BK) * AS + 2 * (idx / BK)) = pk2(v, v);
    }
#pragma unroll
    for (int j = 0; j < WLD; j++) {
        int idx = tid + j * THREADS;
        sW[(idx / BN) * BN + idx % BN] = wload(idx / BN, idx % BN);
    }
    __syncthreads();
    const int niter = K / BK;
    for (int it = 0; it < niter; ++it) {
        float ra[ALD], rw[WLD];
        if (it + 1 < niter) {
            const int kb = (it + 1) * BK;
#pragma unroll
            for (int j = 0; j < ALD; j++) {
                int idx = tid + j * THREADS;
                ra[j] = aload(kb + idx % BK, idx / BK);
            }
#pragma unroll
            for (int j = 0; j < WLD; j++) {
                int idx = tid + j * THREADS;
                rw[j] = wload(kb + idx / BN, idx % BN);
            }
        }
        const float *A0 = sA + (it & 1) * BK * AS;
        const float *W0 = sW + (it & 1) * BK * BN;
#pragma unroll
        for (int kk = 0; kk < BK; kk++) {
            ull au[TM];
            const ulonglong2 *ap = (const ulonglong2 *)(A0 + kk * AS + 2 * ty * TM);
#pragma unroll
            for (int i = 0; i < TM / 2; i++) {
                ulonglong2 v = ap[i]; au[2 * i] = v.x; au[2 * i + 1] = v.y;
            }
            ull wv[TN2];
            const ull *wp = (const ull *)(W0 + kk * BN + tx * TN);
#pragma unroll
            for (int j = 0; j < TN2; j++) wv[j] = wp[j];
#pragma unroll
            for (int i = 0; i < TM; i++)
#pragma unroll
                for (int j = 0; j < TN2; j++) fma2(acc[i][j], au[i], wv[j]);
        }
        if (it + 1 < niter) {
            float *An = sA + ((it + 1) & 1) * BK * AS;
            float *Wn = sW + ((it + 1) & 1) * BK * BN;
#pragma unroll
            for (int j = 0; j < ALD; j++) {
                int idx = tid + j * THREADS;
                *(ull *)(An + (idx % BK) * AS + 2 * (idx / BK)) = pk2(ra[j], ra[j]);
            }
#pragma unroll
            for (int j = 0; j < WLD; j++) {
                int idx = tid + j * THREADS;
                Wn[(idx / BN) * BN + idx % BN] = rw[j];
            }
            __syncthreads();
        }
    }
#pragma unroll
    for (int i = 0; i < TM; i++)
#pragma unroll
        for (int j = 0; j < TN2; j++) {
            float lo, hi; upk2(acc[i][j], lo, hi);
            epi(ty * TM + i, tx * TN + 2 * j, lo);
            epi(ty * TM + i, tx * TN + 2 * j + 1, hi);
        }
}

__global__ void k_init() {
    int i = blockIdx.x * blockDim.x + threadIdx.x;
    if (i < BH) { g_H0B[1][i] = 0.f; g_H1[i] = 0.f; }
    if (i == 0) g_cnt = 0u;
}

#define BIG_SA (2 * 16 * 132)
#define BIG_SW (2 * 16 * 128)

__global__ __launch_bounds__(256) void k_cnn(const float *cnn,
    const float *wu, const float *wr, const float *wc,
    const float *bu, const float *br, const float *bc)
{
    __shared__ __align__(16) float sA[BIG_SA];
    __shared__ __align__(16) float sW[BIG_SW];
    int g = blockIdx.z, m0 = (blockIdx.x & 1) * 64, n0 = (blockIdx.x >> 1) * 128;
    const float *W    = (g == 0 ? wu : g == 1 ? wr : wc) + 1024 * 512;
    const float *bias = (g == 0 ? bu : g == 1 ? br : bc);
    float *Cout = g_C[g];
    core<64, 128, 16, 8, 4, 256>(sA, sW, threadIdx.x, 512,
        [&](int k, int m) { return cnn[(m0 + m) * 512 + k]; },
        [&](int k, int n) { return W[k * 512 + n0 + n]; },
        [&](int mi, int nj, float v) {
            Cout[(m0 + mi) * 512 + n0 + nj] = v + bias[n0 + nj]; });
}

__global__ __launch_bounds__(256) void k_embed(const int *tokens, const float *emb,
    const float *wu, const float *wr, const float *wc)
{
    __shared__ __align__(16) float sA[BIG_SA];
    __shared__ __align__(16) float sW[BIG_SW];
    __shared__ int rowtok[128];
    int g = blockIdx.z, t = blockIdx.y;
    int m0 = (blockIdx.x & 1) * 64, n0 = (blockIdx.x >> 1) * 128;
    if (threadIdx.x < 128) rowtok[threadIdx.x] = tokens[threadIdx.x * Tq + t];
    __syncthreads();
    const float *W  = (g == 0 ? wu : g == 1 ? wr : wc) + 512 * 512;
    const float *Cg = g_C[g];
    float *Pg = g_P[g] + (size_t)t * BH;
    core<64, 128, 16, 8, 4, 256>(sA, sW, threadIdx.x, 512,
        [&](int k, int m) { return emb[(size_t)rowtok[m0 + m] * 512 + k]; },
        [&](int k, int n) { return W[k * 512 + n0 + n]; },
        [&](int mi, int nj, float v) {
            int idx = (m0 + mi) * 512 + n0 + nj;
            Pg[idx] = v + Cg[idx];
        });
}

__global__ __launch_bounds__(256) void k_logits(const float *ow, const float *ob, float *out)
{
    __shared__ __align__(16) float sA[BIG_SA];
    __shared__ __align__(16) float sW[BIG_SW];
    int t = blockIdx.y;
    int m0 = (blockIdx.x & 1) * 64, n0 = (blockIdx.x >> 1) * 128;
    const float *A = g_H1seq + (size_t)t * BH;
    core<64, 128, 16, 8, 4, 256>(sA, sW, threadIdx.x, 512,
        [&](int k, int m) { return A[(m0 + m) * 512 + k]; },
        [&](int k, int n) { int c = n0 + n; return (c < VOCq) ? ow[(size_t)k * VOCq + c] : 0.f; },
        [&](int mi, int nj, float v) {
            int c = n0 + nj;
            if (c < VOCq) out[((size_t)(m0 + mi) * Tq + t) * VOCq + c] = v + ob[c];
        });
}

__global__ void k_hidden(float *out)
{
    int i = blockIdx.x * blockDim.x + threadIdx.x;
    if (i < BH) { out[i] = g_H0B[1][i]; out[BH + i] = g_H1[i]; }
}

extern "C" void kernel_launch(void *const *d_in, const int *in_sizes, int n_in,
                              void *d_out, int out_size)
{
    const int   *tokens = (const int *)  d_in[0];
    const float *cnn    = (const float *)d_in[1];
    const float *emb    = (const float *)d_in[2];
    const float *wu0 = (const float *)d_in[3],  *bu0 = (const float *)d_in[4];
    const float *wr0 = (const float *)d_in[5],  *br0 = (const float *)d_in[6];
    const float *wc0 = (const float *)d_in[7],  *bc0 = (const float *)d_in[8];
    const float *wu1 = (const float *)d_in[9],  *bu1 = (const float *)d_in[10];
    const float *wr1 = (const float *)d_in[11], *br1 = (const float *)d_in[12];
    const float *wc1 = (const float *)d_in[13], *bc1 = (const float *)d_in[14];
    const float *ow  = (const float *)d_in[15], *ob  = (const float *)d_in[16];
    float *out = (float *)d_out;

    k_init<<<128, 512>>>();
    k_cnn  <<<dim3(8, 1, 3),  256>>>(cnn, wu0, wr0, wc0, bu0, br0, bc0);
    k_embed<<<dim3(8, Tq, 3), 256>>>(tokens, emb, wu0, wr0, wc0);

    k_recur<<<NBLK, 512>>>(wu0, wr0, wc0, wu1, bu1, wr1, br1, wc1, bc1);

    k_logits<<<dim3(158, Tq), 256>>>(ow, ob, out);

    if (out_size >= (int)((size_t)Tq * 128 * VOCq + 2 * BH)) {
        k_hidden<<<128, 512>>>(out + (size_t)Tq * 128 * VOCq);
    }
}

// round 9
// speedup vs baseline: 1.1702x; 1.1702x over previous
#include <cuda_runtime.h>

typedef unsigned long long ull;

#define NBLK 128
#define BH   65536
#define Tq   40
#define VOCq 10000

__device__ float g_P[3][Tq * BH];
__device__ float g_C[3][BH];
__device__ float g_H0B[2][BH];
__device__ float g_H1[BH];
__device__ float g_Z0[BH];
__device__ float g_RH0[BH];
__device__ float g_Z1[BH];
__device__ float g_RH1[BH];
__device__ float g_H1seq[Tq * BH];
__device__ unsigned g_cnt;

__device__ __forceinline__ ull pk2(float x, float y) {
    ull r; asm("mov.b64 %0, {%1,%2};" : "=l"(r) : "f"(x), "f"(y)); return r;
}
__device__ __forceinline__ void upk2(ull v, float &x, float &y) {
    asm("mov.b64 {%0,%1}, %2;" : "=f"(x), "=f"(y) : "l"(v));
}
__device__ __forceinline__ void fma2(ull &c, ull a, ull b) {
    asm("fma.rn.f32x2 %0, %1, %2, %3;" : "=l"(c) : "l"(a), "l"(b), "l"(c));
}

// grid barrier with nanosleep backoff (kills L2 poll contention)
__device__ __forceinline__ void gridbar(unsigned &target) {
    __syncthreads();
    target += NBLK;
    if (threadIdx.x == 0) {
        asm volatile("red.release.gpu.add.u32 [%0], %1;" :: "l"(&g_cnt), "r"(1u) : "memory");
        unsigned v, ns = 64;
        while (true) {
            asm volatile("ld.acquire.gpu.u32 %0, [%1];" : "=r"(v) : "l"(&g_cnt) : "memory");
            if ((int)(v - target) >= 0) break;
            __nanosleep(ns);
            if (ns < 256) ns <<= 1;
        }
    }
    __syncthreads();
}

// ---------------- unified recurrence tile (R7 form, unchanged) ----------------
template<int BM>
__device__ __noinline__ void gtile(float *sA, float *sW, int m0, int n0, int K,
    const float *A1, const float *A2, const float *W,
    const float *addRow, const float *addMat, int mode,
    const float *mulS, const float *hPrev, const float *zG,
    float *dst, float *dst2)
{
    constexpr int BK = 32, BN = 64, TM = BM / 8, AS = 2 * BM + 4;
    constexpr int ALD = BM * BK / 256;
    const int tid = threadIdx.x, tx = tid & 31, ty = tid >> 5;

    __syncthreads();

    ull acc[TM];
#pragma unroll
    for (int i = 0; i < TM; i++) acc[i] = 0ull;

    auto ald = [&](int kb, int j) -> float {
        int idx = tid + j * 256;
        int k = kb + (idx & 31), m = m0 + (idx >> 5);
        const float *b = (k < 512) ? A1 : A2;
        return b[m * 512 + (k & 511)];
    };

    float ra[ALD]; float4 rw[2];
#pragma unroll
    for (int j = 0; j < ALD; j++) ra[j] = ald(0, j);
#pragma unroll
    for (int j = 0; j < 2; j++) {
        int q = tid + j * 256;
        rw[j] = *(const float4 *)(W + (size_t)(q >> 4) * 512 + n0 + (q & 15) * 4);
    }
#pragma unroll
    for (int j = 0; j < ALD; j++) {
        int idx = tid + j * 256;
        *(ull *)(sA + (idx & 31) * AS + 2 * (idx >> 5)) = pk2(ra[j], ra[j]);
    }
#pragma unroll
    for (int j = 0; j < 2; j++) {
        int q = tid + j * 256;
        *(float4 *)(sW + (q >> 4) * 64 + (q & 15) * 4) = rw[j];
    }
    __syncthreads();

    const int niter = K >> 5;
    for (int it = 0; it < niter; ++it) {
        if (it + 1 < niter) {
            int kb = (it + 1) << 5;
#pragma unroll
            for (int j = 0; j < ALD; j++) ra[j] = ald(kb, j);
#pragma unroll
            for (int j = 0; j < 2; j++) {
                int q = tid + j * 256;
                rw[j] = *(const float4 *)(W + (size_t)(kb + (q >> 4)) * 512 + n0 + (q & 15) * 4);
            }
        }
        const float *A0 = sA + (it & 1) * BK * AS;
        const float *W0 = sW + (it & 1) * BK * BN;
#pragma unroll
        for (int kk = 0; kk < BK; kk++) {
            ull au[TM];
            const ulonglong2 *ap = (const ulonglong2 *)(A0 + kk * AS + 2 * ty * TM);
#pragma unroll
            for (int i = 0; i < TM / 2; i++) {
                ulonglong2 v = ap[i]; au[2 * i] = v.x; au[2 * i + 1] = v.y;
            }
            ull wv = *(const ull *)(W0 + kk * BN + tx * 2);
#pragma unroll
            for (int i = 0; i < TM; i++) fma2(acc[i], au[i], wv);
        }
        if (it + 1 < niter) {
            float *An = sA + ((it + 1) & 1) * BK * AS;
            float *Wn = sW + ((it + 1) & 1) * BK * BN;
#pragma unroll
            for (int j = 0; j < ALD; j++) {
                int idx = tid + j * 256;
                *(ull *)(An + (idx & 31) * AS + 2 * (idx >> 5)) = pk2(ra[j], ra[j]);
            }
#pragma unroll
            for (int j = 0; j < 2; j++) {
                int q = tid + j * 256;
                *(float4 *)(Wn + (q >> 4) * 64 + (q & 15) * 4) = rw[j];
            }
            __syncthreads();
        }
    }

#pragma unroll
    for (int i = 0; i < TM; i++) {
        float lh[2]; upk2(acc[i], lh[0], lh[1]);
        int row = m0 + ty * TM + i, c0 = n0 + tx * 2;
#pragma unroll
        for (int e = 0; e < 2; e++) {
            int c = c0 + e, idx = row * 512 + c;
            float x = lh[e] + (addRow ? addRow[c] : addMat[idx]);
            if (mode == 0) {
                float s = __fdividef(1.f, 1.f + __expf(-x));
                dst[idx] = mulS ? s * mulS[idx] : s;
            } else {
                float ex = __expf(2.f * x);
                float hh = 1.f - __fdividef(2.f, ex + 1.f);
                float z = zG[idx];
                float hn = z * hPrev[idx] + (1.f - z) * hh;
                dst[idx] = hn;
                if (dst2) dst2[idx] = hn;
            }
        }
    }
}

// ---------------- persistent recurrence (R7 topology, 256 thr) ----------------
__global__ __launch_bounds__(256, 2) void k_recur(
    const float *wu0, const float *wr0, const float *wc0,
    const float *wu1, const float *bu1, const float *wr1, const float *br1,
    const float *wc1, const float *bc1)
{
    __shared__ __align__(16) float sA[2 * 32 * 68];
    __shared__ __align__(16) float sW[2 * 32 * 64];
    unsigned target = 0;
    const int b = blockIdx.x;

    auto ZR = [&](int t) {
        if (b < 64) {                                   // ZR1(t), K=1024
            if (t < 0) return;
            int gate = b >> 5, id = b & 31;
            int m0 = (id >> 3) * 32, n0 = (id & 7) * 64;
            gtile<32>(sA, sW, m0, n0, 1024, g_H1, g_H0B[t & 1],
                      gate ? wr1 : wu1, gate ? br1 : bu1, nullptr, 0,
                      gate ? (const float *)g_H1 : nullptr, nullptr, nullptr,
                      gate ? g_RH1 : g_Z1, nullptr);
        } else {                                        // ZR0(t+1), K=512
            int tn = t + 1;
            if (tn > 39) return;
            int s = b - 64, gate = s >> 5, id = s & 31;
            int m0 = (id >> 3) * 32, n0 = (id & 7) * 64;
            const float *Hp = g_H0B[t & 1];             // t=-1 -> buf1 (zeros)
            gtile<32>(sA, sW, m0, n0, 512, Hp, Hp,
                      gate ? wr0 : wu0, nullptr, g_P[gate] + (size_t)tn * BH, 0,
                      gate ? Hp : nullptr, nullptr, nullptr,
                      gate ? g_RH0 : g_Z0, nullptr);
        }
    };
    auto HP = [&](int t) {
        if (b < 64) {                                   // H1(t-1), K=1024
            int tp = t - 1;
            if (tp < 0) return;
            int m0 = (b >> 3) * 16, n0 = (b & 7) * 64;
            gtile<16>(sA, sW, m0, n0, 1024, g_RH1, g_H0B[tp & 1], wc1,
                      bc1, nullptr, 1, nullptr, g_H1, g_Z1,
                      g_H1, g_H1seq + (size_t)tp * BH);
        } else {                                        // H0(t), K=512
            if (t > 39) return;
            int s = b - 64, m0 = (s >> 3) * 16, n0 = (s & 7) * 64;
            gtile<16>(sA, sW, m0, n0, 512, g_RH0, g_RH0, wc0,
                      nullptr, g_P[2] + (size_t)t * BH, 1,
                      nullptr, g_H0B[(t - 1) & 1], g_Z0,
                      g_H0B[t & 1], nullptr);
        }
    };

    ZR(-1); gridbar(target);
    for (int t = 0; t < Tq; t++) {
        HP(t); gridbar(target);
        ZR(t); gridbar(target);
    }
    HP(Tq);
}

// ---------------- big parallel GEMM core (unchanged) ----------------
template<int BM, int BN, int BK, int TM, int TN, int THREADS,
         class AF, class WF, class EF>
__device__ __forceinline__ void core(float *sA, float *sW, int tid,
                                     int K, AF aload, WF wload, EF epi)
{
    constexpr int NT = BN / TN, MT = BM / TM, TN2 = TN / 2;
    constexpr int AS = 2 * BM + 4;
    constexpr int ALD = BM * BK / THREADS, WLD = BK * BN / THREADS;
    static_assert(NT * MT == THREADS, "");
    const int tx = tid % NT, ty = tid / NT;
    __syncthreads();
    ull acc[TM][TN2];
#pragma unroll
    for (int i = 0; i < TM; i++)
#pragma unroll
        for (int j = 0; j < TN2; j++) acc[i][j] = 0ull;
#pragma unroll
    for (int j = 0; j < ALD; j++) {
        int idx = tid + j * THREADS;
        float v = aload(idx % BK, idx / BK);
        *(ull *)(sA + (idx % BK) * AS + 2 * (idx / BK)) = pk2(v, v);
    }
#pragma unroll
    for (int j = 0; j < WLD; j++) {
        int idx = tid + j * THREADS;
        sW[(idx / BN) * BN + idx % BN] = wload(idx / BN, idx % BN);
    }
    __syncthreads();
    const int niter = K / BK;
    for (int it = 0; it < niter; ++it) {
        float ra[ALD], rw[WLD];
        if (it + 1 < niter) {
            const int kb = (it + 1) * BK;
#pragma unroll
            for (int j = 0; j < ALD; j++) {
                int idx = tid + j * THREADS;
                ra[j] = aload(kb + idx % BK, idx / BK);
            }
#pragma unroll
            for (int j = 0; j < WLD; j++) {
                int idx = tid + j * THREADS;
                rw[j] = wload(kb + idx / BN, idx % BN);
            }
        }
        const float *A0 = sA + (it & 1) * BK * AS;
        const float *W0 = sW + (it & 1) * BK * BN;
#pragma unroll
        for (int kk = 0; kk < BK; kk++) {
            ull au[TM];
            const ulonglong2 *ap = (const ulonglong2 *)(A0 + kk * AS + 2 * ty * TM);
#pragma unroll
            for (int i = 0; i < TM / 2; i++) {
                ulonglong2 v = ap[i]; au[2 * i] = v.x; au[2 * i + 1] = v.y;
            }
            ull wv[TN2];
            const ull *wp = (const ull *)(W0 + kk * BN + tx * TN);
#pragma unroll
            for (int j = 0; j < TN2; j++) wv[j] = wp[j];
#pragma unroll
            for (int i = 0; i < TM; i++)
#pragma unroll
                for (int j = 0; j < TN2; j++) fma2(acc[i][j], au[i], wv[j]);
        }
        if (it + 1 < niter) {
            float *An = sA + ((it + 1) & 1) * BK * AS;
            float *Wn = sW + ((it + 1) & 1) * BK * BN;
#pragma unroll
            for (int j = 0; j < ALD; j++) {
                int idx = tid + j * THREADS;
                *(ull *)(An + (idx % BK) * AS + 2 * (idx / BK)) = pk2(ra[j], ra[j]);
            }
#pragma unroll
            for (int j = 0; j < WLD; j++) {
                int idx = tid + j * THREADS;
                Wn[(idx / BN) * BN + idx % BN] = rw[j];
            }
            __syncthreads();
        }
    }
#pragma unroll
    for (int i = 0; i < TM; i++)
#pragma unroll
        for (int j = 0; j < TN2; j++) {
            float lo, hi; upk2(acc[i][j], lo, hi);
            epi(ty * TM + i, tx * TN + 2 * j, lo);
            epi(ty * TM + i, tx * TN + 2 * j + 1, hi);
        }
}

__global__ void k_init() {
    int i = blockIdx.x * blockDim.x + threadIdx.x;
    if (i < BH) { g_H0B[1][i] = 0.f; g_H1[i] = 0.f; }
    if (i == 0) g_cnt = 0u;
}

#define BIG_SA (2 * 16 * 132)
#define BIG_SW (2 * 16 * 128)

__global__ __launch_bounds__(256) void k_cnn(const float *cnn,
    const float *wu, const float *wr, const float *wc,
    const float *bu, const float *br, const float *bc)
{
    __shared__ __align__(16) float sA[BIG_SA];
    __shared__ __align__(16) float sW[BIG_SW];
    int g = blockIdx.z, m0 = (blockIdx.x & 1) * 64, n0 = (blockIdx.x >> 1) * 128;
    const float *W    = (g == 0 ? wu : g == 1 ? wr : wc) + 1024 * 512;
    const float *bias = (g == 0 ? bu : g == 1 ? br : bc);
    float *Cout = g_C[g];
    core<64, 128, 16, 8, 4, 256>(sA, sW, threadIdx.x, 512,
        [&](int k, int m) { return cnn[(m0 + m) * 512 + k]; },
        [&](int k, int n) { return W[k * 512 + n0 + n]; },
        [&](int mi, int nj, float v) {
            Cout[(m0 + mi) * 512 + n0 + nj] = v + bias[n0 + nj]; });
}

__global__ __launch_bounds__(256) void k_embed(const int *tokens, const float *emb,
    const float *wu, const float *wr, const float *wc)
{
    __shared__ __align__(16) float sA[BIG_SA];
    __shared__ __align__(16) float sW[BIG_SW];
    __shared__ int rowtok[128];
    int g = blockIdx.z, t = blockIdx.y;
    int m0 = (blockIdx.x & 1) * 64, n0 = (blockIdx.x >> 1) * 128;
    if (threadIdx.x < 128) rowtok[threadIdx.x] = tokens[threadIdx.x * Tq + t];
    __syncthreads();
    const float *W  = (g == 0 ? wu : g == 1 ? wr : wc) + 512 * 512;
    const float *Cg = g_C[g];
    float *Pg = g_P[g] + (size_t)t * BH;
    core<64, 128, 16, 8, 4, 256>(sA, sW, threadIdx.x, 512,
        [&](int k, int m) { return emb[(size_t)rowtok[m0 + m] * 512 + k]; },
        [&](int k, int n) { return W[k * 512 + n0 + n]; },
        [&](int mi, int nj, float v) {
            int idx = (m0 + mi) * 512 + n0 + nj;
            Pg[idx] = v + Cg[idx];
        });
}

__global__ __launch_bounds__(256) void k_logits(const float *ow, const float *ob, float *out)
{
    __shared__ __align__(16) float sA[BIG_SA];
    __shared__ __align__(16) float sW[BIG_SW];
    int t = blockIdx.y;
    int m0 = (blockIdx.x & 1) * 64, n0 = (blockIdx.x >> 1) * 128;
    const float *A = g_H1seq + (size_t)t * BH;
    core<64, 128, 16, 8, 4, 256>(sA, sW, threadIdx.x, 512,
        [&](int k, int m) { return A[(m0 + m) * 512 + k]; },
        [&](int k, int n) { int c = n0 + n; return (c < VOCq) ? ow[(size_t)k * VOCq + c] : 0.f; },
        [&](int mi, int nj, float v) {
            int c = n0 + nj;
            if (c < VOCq) out[((size_t)(m0 + mi) * Tq + t) * VOCq + c] = v + ob[c];
        });
}

__global__ void k_hidden(float *out)
{
    int i = blockIdx.x * blockDim.x + threadIdx.x;
    if (i < BH) { out[i] = g_H0B[1][i]; out[BH + i] = g_H1[i]; }
}

extern "C" void kernel_launch(void *const *d_in, const int *in_sizes, int n_in,
                              void *d_out, int out_size)
{
    const int   *tokens = (const int *)  d_in[0];
    const float *cnn    = (const float *)d_in[1];
    const float *emb    = (const float *)d_in[2];
    const float *wu0 = (const float *)d_in[3],  *bu0 = (const float *)d_in[4];
    const float *wr0 = (const float *)d_in[5],  *br0 = (const float *)d_in[6];
    const float *wc0 = (const float *)d_in[7],  *bc0 = (const float *)d_in[8];
    const float *wu1 = (const float *)d_in[9],  *bu1 = (const float *)d_in[10];
    const float *wr1 = (const float *)d_in[11], *br1 = (const float *)d_in[12];
    const float *wc1 = (const float *)d_in[13], *bc1 = (const float *)d_in[14];
    const float *ow  = (const float *)d_in[15], *ob  = (const float *)d_in[16];
    float *out = (float *)d_out;

    k_init<<<128, 512>>>();
    k_cnn  <<<dim3(8, 1, 3),  256>>>(cnn, wu0, wr0, wc0, bu0, br0, bc0);
    k_embed<<<dim3(8, Tq, 3), 256>>>(tokens, emb, wu0, wr0, wc0);

    k_recur<<<NBLK, 256>>>(wu0, wr0, wc0, wu1, bu1, wr1, br1, wc1, bc1);

    k_logits<<<dim3(158, Tq), 256>>>(ow, ob, out);

    if (out_size >= (int)((size_t)Tq * 128 * VOCq + 2 * BH)) {
        k_hidden<<<128, 512>>>(out + (size_t)Tq * 128 * VOCq);
    }
}